// round 6
// baseline (speedup 1.0000x reference)
#include <cuda_runtime.h>

// out[b, d] = initial[b, d] * (sum_k X[b,k]*alphas[k]) + X[b,d] + bias[d]
// B = 16384 rows, D = 2048 cols, fp32.
//
// FOUR rows per CTA: 256 threads, each thread covers 2 float4 per row per
// array -> 16 streaming LDG.128 front-batched per thread (deep MLP). One
// barrier + one smem round-trip serves all four row reductions. Grid = B/4.

#define THREADS 256
#define D_DIM 2048
#define D4 (D_DIM / 4)          // 512 float4 per row
#define NWARPS (THREADS / 32)   // 8
#define ROWS_PER_CTA 4

__global__ __launch_bounds__(THREADS, 2)
void crossnet_kernel(const float* __restrict__ initial,
                     const float* __restrict__ X,
                     const float* __restrict__ alphas,
                     const float* __restrict__ bias,
                     float* __restrict__ out)
{
    const int t = threadIdx.x;
    const int lane = t & 31;
    const int wid = t >> 5;

    const size_t rbase = (size_t)(ROWS_PER_CTA * blockIdx.x) * D4;

    const float4* __restrict__ X4 = reinterpret_cast<const float4*>(X);
    const float4* __restrict__ I4 = reinterpret_cast<const float4*>(initial);
    const float4* __restrict__ A4 = reinterpret_cast<const float4*>(alphas);
    const float4* __restrict__ B4 = reinterpret_cast<const float4*>(bias);
    float4* __restrict__ O4 = reinterpret_cast<float4*>(out);

    // Front-batched streaming loads: 4 rows of X and initial (16 LDG.128).
    float4 x[ROWS_PER_CTA][2], iv[ROWS_PER_CTA][2];
    #pragma unroll
    for (int r = 0; r < ROWS_PER_CTA; r++) {
        x[r][0] = __ldcs(&X4[rbase + (size_t)r * D4 + t]);
        x[r][1] = __ldcs(&X4[rbase + (size_t)r * D4 + t + THREADS]);
    }
    #pragma unroll
    for (int r = 0; r < ROWS_PER_CTA; r++) {
        iv[r][0] = __ldcs(&I4[rbase + (size_t)r * D4 + t]);
        iv[r][1] = __ldcs(&I4[rbase + (size_t)r * D4 + t + THREADS]);
    }
    float4 a0 = A4[t];
    float4 a1 = A4[t + THREADS];
    float4 b0 = B4[t];
    float4 b1 = B4[t + THREADS];

    // Per-thread partial dot products.
    float dot[ROWS_PER_CTA];
    #pragma unroll
    for (int r = 0; r < ROWS_PER_CTA; r++) {
        dot[r] = x[r][0].x * a0.x + x[r][0].y * a0.y
               + x[r][0].z * a0.z + x[r][0].w * a0.w
               + x[r][1].x * a1.x + x[r][1].y * a1.y
               + x[r][1].z * a1.z + x[r][1].w * a1.w;
    }

    // Warp reduce all rows.
    #pragma unroll
    for (int off = 16; off > 0; off >>= 1) {
        #pragma unroll
        for (int r = 0; r < ROWS_PER_CTA; r++)
            dot[r] += __shfl_xor_sync(0xFFFFFFFFu, dot[r], off);
    }

    // One barrier serves all four rows' block reductions.
    __shared__ float ws[ROWS_PER_CTA][NWARPS];
    if (lane == 0) {
        #pragma unroll
        for (int r = 0; r < ROWS_PER_CTA; r++) ws[r][wid] = dot[r];
    }
    __syncthreads();

    float s[ROWS_PER_CTA];
    #pragma unroll
    for (int r = 0; r < ROWS_PER_CTA; r++)
        s[r] = (lane < NWARPS) ? ws[r][lane] : 0.0f;
    #pragma unroll
    for (int off = NWARPS / 2; off > 0; off >>= 1) {
        #pragma unroll
        for (int r = 0; r < ROWS_PER_CTA; r++)
            s[r] += __shfl_xor_sync(0xFFFFFFFFu, s[r], off);
    }

    #pragma unroll
    for (int r = 0; r < ROWS_PER_CTA; r++) {
        const float scale = __shfl_sync(0xFFFFFFFFu, s[r], 0);
        float4 o;
        o.x = fmaf(iv[r][0].x, scale, x[r][0].x + b0.x);
        o.y = fmaf(iv[r][0].y, scale, x[r][0].y + b0.y);
        o.z = fmaf(iv[r][0].z, scale, x[r][0].z + b0.z);
        o.w = fmaf(iv[r][0].w, scale, x[r][0].w + b0.w);
        __stcs(&O4[rbase + (size_t)r * D4 + t], o);

        o.x = fmaf(iv[r][1].x, scale, x[r][1].x + b1.x);
        o.y = fmaf(iv[r][1].y, scale, x[r][1].y + b1.y);
        o.z = fmaf(iv[r][1].z, scale, x[r][1].z + b1.z);
        o.w = fmaf(iv[r][1].w, scale, x[r][1].w + b1.w);
        __stcs(&O4[rbase + (size_t)r * D4 + t + THREADS], o);
    }
}

extern "C" void kernel_launch(void* const* d_in, const int* in_sizes, int n_in,
                              void* d_out, int out_size)
{
    const float* initial = (const float*)d_in[0];
    const float* X       = (const float*)d_in[1];
    const float* alphas  = (const float*)d_in[2];
    const float* bias    = (const float*)d_in[3];
    float* out           = (float*)d_out;

    const int B = in_sizes[0] / D_DIM;   // 16384
    crossnet_kernel<<<B / ROWS_PER_CTA, THREADS>>>(initial, X, alphas, bias, out);
}

// round 7
// speedup vs baseline: 1.0211x; 1.0211x over previous
#include <cuda_runtime.h>

// out[b, d] = initial[b, d] * (sum_k X[b,k]*alphas[k]) + X[b,d] + bias[d]
// B = 16384 rows, D = 2048 cols, fp32.
//
// TWO rows per CTA, 512 threads: each thread covers exactly 1 float4 per row
// per array (low register pressure -> 3 CTAs/SM, 75% occupancy) while one
// barrier + one smem round-trip still serves both row reductions.

#define THREADS 512
#define D_DIM 2048
#define D4 (D_DIM / 4)          // 512 float4 per row == THREADS
#define NWARPS (THREADS / 32)   // 16

__global__ __launch_bounds__(THREADS, 3)
void crossnet_kernel(const float* __restrict__ initial,
                     const float* __restrict__ X,
                     const float* __restrict__ alphas,
                     const float* __restrict__ bias,
                     float* __restrict__ out)
{
    const int t = threadIdx.x;
    const int lane = t & 31;
    const int wid = t >> 5;

    const size_t base0 = (size_t)(2 * blockIdx.x) * D4;
    const size_t base1 = base0 + D4;

    const float4* __restrict__ X4 = reinterpret_cast<const float4*>(X);
    const float4* __restrict__ I4 = reinterpret_cast<const float4*>(initial);
    const float4* __restrict__ A4 = reinterpret_cast<const float4*>(alphas);
    const float4* __restrict__ B4 = reinterpret_cast<const float4*>(bias);
    float4* __restrict__ O4 = reinterpret_cast<float4*>(out);

    // Front-batched loads: 4 streaming LDG.128 + 2 cached (alphas/bias hot).
    float4 x0 = __ldcs(&X4[base0 + t]);
    float4 x1 = __ldcs(&X4[base1 + t]);
    float4 i0 = __ldcs(&I4[base0 + t]);
    float4 i1 = __ldcs(&I4[base1 + t]);
    float4 a  = A4[t];
    float4 b  = B4[t];

    // Per-thread partial dot products for both rows.
    float dot0 = x0.x * a.x + x0.y * a.y + x0.z * a.z + x0.w * a.w;
    float dot1 = x1.x * a.x + x1.y * a.y + x1.z * a.z + x1.w * a.w;

    // Warp reduce both rows.
    #pragma unroll
    for (int off = 16; off > 0; off >>= 1) {
        dot0 += __shfl_xor_sync(0xFFFFFFFFu, dot0, off);
        dot1 += __shfl_xor_sync(0xFFFFFFFFu, dot1, off);
    }

    // Single-barrier block reduce over 16 warps; every warp folds the
    // partials redundantly via shuffle (no second barrier).
    __shared__ float ws0[NWARPS];
    __shared__ float ws1[NWARPS];
    if (lane == 0) { ws0[wid] = dot0; ws1[wid] = dot1; }
    __syncthreads();

    float s0 = (lane < NWARPS) ? ws0[lane] : 0.0f;
    float s1 = (lane < NWARPS) ? ws1[lane] : 0.0f;
    #pragma unroll
    for (int off = NWARPS / 2; off > 0; off >>= 1) {
        s0 += __shfl_xor_sync(0xFFFFFFFFu, s0, off);
        s1 += __shfl_xor_sync(0xFFFFFFFFu, s1, off);
    }
    const float scale0 = __shfl_sync(0xFFFFFFFFu, s0, 0);
    const float scale1 = __shfl_sync(0xFFFFFFFFu, s1, 0);

    float4 o;
    o.x = fmaf(i0.x, scale0, x0.x + b.x);
    o.y = fmaf(i0.y, scale0, x0.y + b.y);
    o.z = fmaf(i0.z, scale0, x0.z + b.z);
    o.w = fmaf(i0.w, scale0, x0.w + b.w);
    __stcs(&O4[base0 + t], o);

    o.x = fmaf(i1.x, scale1, x1.x + b.x);
    o.y = fmaf(i1.y, scale1, x1.y + b.y);
    o.z = fmaf(i1.z, scale1, x1.z + b.z);
    o.w = fmaf(i1.w, scale1, x1.w + b.w);
    __stcs(&O4[base1 + t], o);
}

extern "C" void kernel_launch(void* const* d_in, const int* in_sizes, int n_in,
                              void* d_out, int out_size)
{
    const float* initial = (const float*)d_in[0];
    const float* X       = (const float*)d_in[1];
    const float* alphas  = (const float*)d_in[2];
    const float* bias    = (const float*)d_in[3];
    float* out           = (float*)d_out;

    const int B = in_sizes[0] / D_DIM;   // 16384
    crossnet_kernel<<<B / 2, THREADS>>>(initial, X, alphas, bias, out);
}